// round 13
// baseline (speedup 1.0000x reference)
#include <cuda_runtime.h>
#include <cuda_bf16.h>
#include <math.h>

#define NN 100000
#define EE 600000
#define NB_SCAN ((NN + 255) / 256)   // 391

// ---------------- static scratch (no allocations allowed) ----------------
__device__ int   g_is64;
__device__ int   g_deg[NN];
__device__ int   g_cur[NN];
__device__ int   g_rowstart[NN + 1];
__device__ int   g_col[EE];
__device__ int   g_part[512];

__device__ __nv_bfloat16 g_xb[(size_t)NN * 128];
__device__ __nv_bfloat16 g_h1b[(size_t)NN * 256];
__device__ __nv_bfloat16 g_h2b[(size_t)NN * 128];
__device__ __nv_bfloat16 g_tb[(size_t)NN * 256];   // bf16 mean-term (Wl half)
__device__ float         g_t[(size_t)NN * 256];    // fp32 self-term (Wr half)
__device__ __nv_bfloat16 g_wt1[512 * 128];
__device__ __nv_bfloat16 g_wt2[256 * 256];
__device__ __nv_bfloat16 g_wt3[128 * 128];

__device__ __forceinline__ __nv_bfloat16* bbuf(int id) {
    switch (id) {
        case 0: return g_xb;
        case 2: return g_h1b;
        case 3: return g_h2b;
        case 4: return g_wt1;
        case 5: return g_wt2;
        default: return g_wt3;
    }
}

// ---------------- init: zero counts + dtype probe (fused) ----------------
__global__ void k_init(const int* __restrict__ w) {
    int i = blockIdx.x * blockDim.x + threadIdx.x;
    if (i < NN) { g_deg[i] = 0; g_cur[i] = 0; }
    if (i == 0) {
        int is64 = 1;
        for (int j = 0; j < 64; j++) {
            if (w[2 * j + 1] != 0) { is64 = 0; break; }
        }
        g_is64 = is64;
    }
}
__device__ __forceinline__ int edge_src(const int* w, int E, int e) {
    return g_is64 ? w[2 * e] : w[e];
}
__device__ __forceinline__ int edge_dst(const int* w, int E, int e) {
    return g_is64 ? w[2 * (E + e)] : w[E + e];
}

// ---------------- CSR build ----------------
__global__ void k_count(const int* __restrict__ w, int E) {
    int e = blockIdx.x * blockDim.x + threadIdx.x;
    if (e < E) atomicAdd(&g_deg[edge_dst(w, E, e)], 1);
}
__global__ void k_part_sum() {
    __shared__ int sm[8];
    int i = blockIdx.x * 256 + threadIdx.x;
    int v = (i < NN) ? g_deg[i] : 0;
#pragma unroll
    for (int off = 16; off; off >>= 1) v += __shfl_xor_sync(0xffffffffu, v, off);
    if ((threadIdx.x & 31) == 0) sm[threadIdx.x >> 5] = v;
    __syncthreads();
    if (threadIdx.x == 0) {
        int s = 0;
#pragma unroll
        for (int k = 0; k < 8; k++) s += sm[k];
        g_part[blockIdx.x] = s;
    }
}
__global__ void k_row_write(int E) {
    __shared__ int red[8];
    __shared__ int buf[256];
    __shared__ int base_sh;
    int t = threadIdx.x;
    int b = blockIdx.x;

    int acc = 0;
    for (int j = t; j < b; j += 256) acc += g_part[j];
#pragma unroll
    for (int off = 16; off; off >>= 1) acc += __shfl_xor_sync(0xffffffffu, acc, off);
    if ((t & 31) == 0) red[t >> 5] = acc;
    __syncthreads();
    if (t == 0) {
        int s = 0;
#pragma unroll
        for (int k = 0; k < 8; k++) s += red[k];
        base_sh = s;
    }

    int i = b * 256 + t;
    int d = (i < NN) ? g_deg[i] : 0;
    buf[t] = d;
    __syncthreads();
    for (int off = 1; off < 256; off <<= 1) {
        int v = (t >= off) ? buf[t - off] : 0;
        __syncthreads();
        buf[t] += v;
        __syncthreads();
    }
    if (i < NN) {
        g_rowstart[i] = base_sh + buf[t] - d;
        if (i == NN - 1) g_rowstart[NN] = E;
    }
}
__global__ void k_fill(const int* __restrict__ w, int E) {
    int e = blockIdx.x * blockDim.x + threadIdx.x;
    if (e < E) {
        int src = edge_src(w, E, e);
        int dst = edge_dst(w, E, e);
        int pos = g_rowstart[dst] + atomicAdd(&g_cur[dst], 1);
        g_col[pos] = src;
    }
}

// ---------------- conversions ----------------
__global__ void k_cvt_x(const float* __restrict__ x) {
    size_t i = (size_t)blockIdx.x * blockDim.x + threadIdx.x;
    if (i < (size_t)NN * 32) {
        float4 v = *(const float4*)(x + i * 4);
        __nv_bfloat162 o0, o1;
        o0.x = __float2bfloat16(v.x); o0.y = __float2bfloat16(v.y);
        o1.x = __float2bfloat16(v.z); o1.y = __float2bfloat16(v.w);
        uint2 ov;
        ov.x = *reinterpret_cast<unsigned*>(&o0);
        ov.y = *reinterpret_cast<unsigned*>(&o1);
        *(uint2*)(g_xb + i * 4) = ov;
    }
}
// dst[n*K2+k]; n<N/2 -> Wl[k*(N/2)+n] else Wr[k*(N/2)+(n-N/2)]
__global__ void k_cvtw(const float* __restrict__ Wl, const float* __restrict__ Wr,
                       int dst_id, int K2, int N) {
    int idx = blockIdx.x * blockDim.x + threadIdx.x;
    if (idx >= N * K2) return;
    int n = idx / K2, k = idx % K2;
    int half = N / 2;
    float v = (n < half) ? Wl[(size_t)k * half + n] : Wr[(size_t)k * half + (n - half)];
    bbuf(dst_id)[(size_t)n * K2 + k] = __float2bfloat16(v);
}

// ---------------- bf16 GEMM: 3-stage cp.async + ldmatrix ----------------
#define SA 40   // smem row stride in halves (80B): 16B-aligned, conflict-free
#define GEMM_SMEM (3 * 256 * SA * 2)   // 61440 bytes

__device__ __forceinline__ void cpa16(__nv_bfloat16* s, const void* g, int valid) {
    unsigned sa = (unsigned)__cvta_generic_to_shared(s);
    asm volatile("cp.async.cg.shared.global [%0], [%1], 16, %2;\n"
                 :: "r"(sa), "l"(g), "r"(valid ? 16 : 0));
}

__global__ void __launch_bounds__(256, 2)
k_gemm_bf16(int a_id, int b_id,
            const float* __restrict__ bias,
            int outb_id,          // >=0: bf16 out buffer id; <0: split bf16/fp32 out
            int M, int N, int K2, int do_relu) {
    const __nv_bfloat16* A = bbuf(a_id);
    const __nv_bfloat16* Bt = bbuf(b_id);

    constexpr int BM = 128, BN = 128, BK = 32;
    extern __shared__ __nv_bfloat16 dsm[];
    __nv_bfloat16* AsB = dsm;
    __nv_bfloat16* BsB = dsm + 3 * BM * SA;

    const int tid  = threadIdx.x;
    const int lane = tid & 31;
    const int warp = tid >> 5;
    const int wm   = warp & 3;
    const int wn   = warp >> 2;
    const int gid  = lane >> 2;
    const int tig  = lane & 3;

    const int blockRow = blockIdx.x * BM;
    const int blockCol = blockIdx.y * BN;

    float c[2][8][4];
#pragma unroll
    for (int mt = 0; mt < 2; mt++)
#pragma unroll
        for (int nt = 0; nt < 8; nt++)
#pragma unroll
            for (int r = 0; r < 4; r++) c[mt][nt][r] = 0.f;

    const int T = K2 / BK;

    auto load_tile = [&](int t, int stg) {
        __nv_bfloat16* As = AsB + stg * BM * SA;
        __nv_bfloat16* Bs = BsB + stg * BN * SA;
        const int kk = t * BK;
#pragma unroll
        for (int j = 0; j < 2; j++) {
            int f = tid + 256 * j;
            int r = f >> 2, c16 = f & 3;
            int gk = kk + c16 * 8;
            int grow = blockRow + r;
            int valid = grow < M;
            int rr = valid ? grow : 0;
            cpa16(&As[r * SA + c16 * 8], A + (size_t)rr * K2 + gk, valid);
        }
#pragma unroll
        for (int j = 0; j < 2; j++) {
            int f = tid + 256 * j;
            int r = f >> 2, c16 = f & 3;
            int gk = kk + c16 * 8;
            cpa16(&Bs[r * SA + c16 * 8], Bt + (size_t)(blockCol + r) * K2 + gk, 1);
        }
        asm volatile("cp.async.commit_group;\n");
    };

    load_tile(0, 0);
    if (T > 1) load_tile(1, 1);

    for (int t = 0; t < T; t++) {
        if (t + 1 < T) {
            asm volatile("cp.async.wait_group 1;\n");
        } else {
            asm volatile("cp.async.wait_group 0;\n");
        }
        __syncthreads();

        const int cur = t % 3;
        const __nv_bfloat16* as = AsB + cur * BM * SA;
        const __nv_bfloat16* bs = BsB + cur * BN * SA;

#pragma unroll
        for (int ks = 0; ks < BK; ks += 16) {
            unsigned af[2][4], bf[8][2];
#pragma unroll
            for (int mt = 0; mt < 2; mt++) {
                int row = wm * 32 + mt * 16 + (lane & 15);
                unsigned sa = (unsigned)__cvta_generic_to_shared(
                    as + row * SA + ks + (lane >> 4) * 8);
                asm volatile("ldmatrix.sync.aligned.m8n8.x4.shared.b16 {%0,%1,%2,%3}, [%4];"
                             : "=r"(af[mt][0]), "=r"(af[mt][1]),
                               "=r"(af[mt][2]), "=r"(af[mt][3])
                             : "r"(sa));
            }
#pragma unroll
            for (int np = 0; np < 4; np++) {
                int nrow = wn * 64 + np * 16 + (lane & 15);
                unsigned sb = (unsigned)__cvta_generic_to_shared(
                    bs + nrow * SA + ks + (lane >> 4) * 8);
                unsigned r0, r1, r2, r3;
                asm volatile("ldmatrix.sync.aligned.m8n8.x4.shared.b16 {%0,%1,%2,%3}, [%4];"
                             : "=r"(r0), "=r"(r1), "=r"(r2), "=r"(r3)
                             : "r"(sb));
                bf[2 * np + 0][0] = r0; bf[2 * np + 0][1] = r2;
                bf[2 * np + 1][0] = r1; bf[2 * np + 1][1] = r3;
            }
#pragma unroll
            for (int mt = 0; mt < 2; mt++)
#pragma unroll
                for (int nt = 0; nt < 8; nt++) {
                    asm volatile(
                        "mma.sync.aligned.m16n8k16.row.col.f32.bf16.bf16.f32 "
                        "{%0,%1,%2,%3}, {%4,%5,%6,%7}, {%8,%9}, {%0,%1,%2,%3};\n"
                        : "+f"(c[mt][nt][0]), "+f"(c[mt][nt][1]),
                          "+f"(c[mt][nt][2]), "+f"(c[mt][nt][3])
                        : "r"(af[mt][0]), "r"(af[mt][1]), "r"(af[mt][2]), "r"(af[mt][3]),
                          "r"(bf[nt][0]), "r"(bf[nt][1]));
                }
        }

        if (t + 2 < T) load_tile(t + 2, (t + 2) % 3);
    }

    // epilogue
    __nv_bfloat16* outb = (outb_id >= 0) ? bbuf(outb_id) : nullptr;
    const int half = N >> 1;
#pragma unroll
    for (int nt = 0; nt < 8; nt++) {
        int col = blockCol + wn * 64 + nt * 8 + 2 * tig;
        float bv0 = bias ? bias[col] : 0.f;
        float bv1 = bias ? bias[col + 1] : 0.f;
#pragma unroll
        for (int mt = 0; mt < 2; mt++) {
#pragma unroll
            for (int h = 0; h < 2; h++) {
                int r = blockRow + wm * 32 + mt * 16 + gid + h * 8;
                if (r < M) {
                    float v0 = c[mt][nt][2 * h + 0] + bv0;
                    float v1 = c[mt][nt][2 * h + 1] + bv1;
                    if (do_relu) { v0 = fmaxf(v0, 0.f); v1 = fmaxf(v1, 0.f); }
                    if (outb) {
                        __nv_bfloat162 o;
                        o.x = __float2bfloat16(v0);
                        o.y = __float2bfloat16(v1);
                        *(unsigned*)(outb + (size_t)r * N + col) =
                            *reinterpret_cast<unsigned*>(&o);
                    } else if (col < half) {
                        __nv_bfloat162 o;
                        o.x = __float2bfloat16(v0);
                        o.y = __float2bfloat16(v1);
                        *(unsigned*)(g_tb + (size_t)r * half + col) =
                            *reinterpret_cast<unsigned*>(&o);
                    } else {
                        float2 o = make_float2(v0, v1);
                        *(float2*)(g_t + (size_t)r * half + (col - half)) = o;
                    }
                }
            }
        }
    }
}

// ---------------- agg-combine: h = act(mean_nb(tb) + t_self + bias) ----------------
// MODE 0: relu -> bf16 bbuf(outid); C in {256, 128}
// MODE 1: log_softmax -> fp32 out; C = 64
template <int C, int MODE>
__global__ void k_agg_combine(const float* __restrict__ bias, float* __restrict__ out,
                              int outid) {
    int gw   = (blockIdx.x * blockDim.x + threadIdx.x) >> 5;
    int lane = threadIdx.x & 31;
    if (gw >= NN) return;
    int s = g_rowstart[gw], e = g_rowstart[gw + 1];

    if constexpr (MODE == 0) {
        constexpr int V = (C >= 128) ? C / 128 : 1;
        float4 acc[V];
#pragma unroll
        for (int v = 0; v < V; v++) acc[v] = make_float4(0.f, 0.f, 0.f, 0.f);
        int i = s;
        for (; i + 1 < e; i += 2) {
            int nb0 = g_col[i], nb1 = g_col[i + 1];
            uint2 va[V], vb[V];
#pragma unroll
            for (int v = 0; v < V; v++) {
                va[v] = *(const uint2*)(g_tb + (size_t)nb0 * C + v * 128 + lane * 4);
                vb[v] = *(const uint2*)(g_tb + (size_t)nb1 * C + v * 128 + lane * 4);
            }
#pragma unroll
            for (int v = 0; v < V; v++) {
                __nv_bfloat162 a0 = *reinterpret_cast<__nv_bfloat162*>(&va[v].x);
                __nv_bfloat162 a1 = *reinterpret_cast<__nv_bfloat162*>(&va[v].y);
                __nv_bfloat162 b0 = *reinterpret_cast<__nv_bfloat162*>(&vb[v].x);
                __nv_bfloat162 b1 = *reinterpret_cast<__nv_bfloat162*>(&vb[v].y);
                float2 fa0 = __bfloat1622float2(a0), fa1 = __bfloat1622float2(a1);
                float2 fb0 = __bfloat1622float2(b0), fb1 = __bfloat1622float2(b1);
                acc[v].x += fa0.x + fb0.x; acc[v].y += fa0.y + fb0.y;
                acc[v].z += fa1.x + fb1.x; acc[v].w += fa1.y + fb1.y;
            }
        }
        if (i < e) {
            int nb = g_col[i];
#pragma unroll
            for (int v = 0; v < V; v++) {
                uint2 va = *(const uint2*)(g_tb + (size_t)nb * C + v * 128 + lane * 4);
                __nv_bfloat162 a0 = *reinterpret_cast<__nv_bfloat162*>(&va.x);
                __nv_bfloat162 a1 = *reinterpret_cast<__nv_bfloat162*>(&va.y);
                float2 f0 = __bfloat1622float2(a0), f1 = __bfloat1622float2(a1);
                acc[v].x += f0.x; acc[v].y += f0.y; acc[v].z += f1.x; acc[v].w += f1.y;
            }
        }
        float inv = 1.0f / (float)max(e - s, 1);
        __nv_bfloat16* ob = bbuf(outid);
#pragma unroll
        for (int v = 0; v < V; v++) {
            float4 sv = *(const float4*)(g_t + (size_t)gw * C + v * 128 + lane * 4);
            float4 bv = *(const float4*)(bias + v * 128 + lane * 4);
            float v0 = fmaxf(acc[v].x * inv + sv.x + bv.x, 0.f);
            float v1 = fmaxf(acc[v].y * inv + sv.y + bv.y, 0.f);
            float v2 = fmaxf(acc[v].z * inv + sv.z + bv.z, 0.f);
            float v3 = fmaxf(acc[v].w * inv + sv.w + bv.w, 0.f);
            __nv_bfloat162 o0, o1;
            o0.x = __float2bfloat16(v0); o0.y = __float2bfloat16(v1);
            o1.x = __float2bfloat16(v2); o1.y = __float2bfloat16(v3);
            uint2 ov;
            ov.x = *reinterpret_cast<unsigned*>(&o0);
            ov.y = *reinterpret_cast<unsigned*>(&o1);
            *(uint2*)(ob + (size_t)gw * C + v * 128 + lane * 4) = ov;
        }
    } else {
        float2 acc = make_float2(0.f, 0.f);
        int i = s;
        for (; i + 1 < e; i += 2) {
            int nb0 = g_col[i], nb1 = g_col[i + 1];
            unsigned va = *(const unsigned*)(g_tb + (size_t)nb0 * C + lane * 2);
            unsigned vb = *(const unsigned*)(g_tb + (size_t)nb1 * C + lane * 2);
            __nv_bfloat162 pa = *reinterpret_cast<__nv_bfloat162*>(&va);
            __nv_bfloat162 pb = *reinterpret_cast<__nv_bfloat162*>(&vb);
            float2 fa = __bfloat1622float2(pa), fb = __bfloat1622float2(pb);
            acc.x += fa.x + fb.x; acc.y += fa.y + fb.y;
        }
        if (i < e) {
            int nb = g_col[i];
            unsigned v = *(const unsigned*)(g_tb + (size_t)nb * C + lane * 2);
            __nv_bfloat162 p = *reinterpret_cast<__nv_bfloat162*>(&v);
            float2 f = __bfloat1622float2(p);
            acc.x += f.x; acc.y += f.y;
        }
        float inv = 1.0f / (float)max(e - s, 1);
        float2 sv = *(const float2*)(g_t + (size_t)gw * C + lane * 2);
        float2 bv = *(const float2*)(bias + lane * 2);
        float v0 = acc.x * inv + sv.x + bv.x;
        float v1 = acc.y * inv + sv.y + bv.y;
        float m = fmaxf(v0, v1);
#pragma unroll
        for (int off = 16; off; off >>= 1) m = fmaxf(m, __shfl_xor_sync(0xffffffffu, m, off));
        float sum = __expf(v0 - m) + __expf(v1 - m);
#pragma unroll
        for (int off = 16; off; off >>= 1) sum += __shfl_xor_sync(0xffffffffu, sum, off);
        float lse = m + __logf(sum);
        float2 o = make_float2(v0 - lse, v1 - lse);
        *(float2*)(out + (size_t)gw * C + lane * 2) = o;
    }
}

// ---------------- launch ----------------
extern "C" void kernel_launch(void* const* d_in, const int* in_sizes, int n_in,
                              void* d_out, int out_size) {
    const float* x   = (const float*)d_in[0];
    const int*   ei  = (const int*)d_in[1];
    const float* W1l = (const float*)d_in[2];
    const float* W1r = (const float*)d_in[3];
    const float* b1  = (const float*)d_in[4];
    const float* W2l = (const float*)d_in[5];
    const float* W2r = (const float*)d_in[6];
    const float* b2  = (const float*)d_in[7];
    const float* W3l = (const float*)d_in[8];
    const float* W3r = (const float*)d_in[9];
    const float* b3  = (const float*)d_in[10];
    float* out = (float*)d_out;

    int E = in_sizes[1] / 2;

    static cudaStream_t s1 = nullptr, s2 = nullptr, s3 = nullptr;
    static cudaEvent_t eFork = nullptr, eCvtX = nullptr, eCvtW = nullptr, eCSR = nullptr;
    if (!s1) {
        cudaStreamCreateWithFlags(&s1, cudaStreamNonBlocking);
        cudaStreamCreateWithFlags(&s2, cudaStreamNonBlocking);
        cudaStreamCreateWithFlags(&s3, cudaStreamNonBlocking);
        cudaEventCreateWithFlags(&eFork, cudaEventDisableTiming);
        cudaEventCreateWithFlags(&eCvtX, cudaEventDisableTiming);
        cudaEventCreateWithFlags(&eCvtW, cudaEventDisableTiming);
        cudaEventCreateWithFlags(&eCSR, cudaEventDisableTiming);
        cudaFuncSetAttribute(k_gemm_bf16,
                             cudaFuncAttributeMaxDynamicSharedMemorySize, GEMM_SMEM);
    }

    // fork
    cudaEventRecord(eFork, 0);
    cudaStreamWaitEvent(s1, eFork, 0);
    cudaStreamWaitEvent(s2, eFork, 0);
    cudaStreamWaitEvent(s3, eFork, 0);

    // s1: x -> bf16
    k_cvt_x<<<(NN * 32 + 255) / 256, 256, 0, s1>>>(x);
    cudaEventRecord(eCvtX, s1);

    // s2: weight transposes -> bf16
    k_cvtw<<<(512 * 128 + 255) / 256, 256, 0, s2>>>(W1l, W1r, 4, 128, 512);
    k_cvtw<<<(256 * 256 + 255) / 256, 256, 0, s2>>>(W2l, W2r, 5, 256, 256);
    k_cvtw<<<(128 * 128 + 255) / 256, 256, 0, s2>>>(W3l, W3r, 6, 128, 128);
    cudaEventRecord(eCvtW, s2);

    // s3: CSR build (hidden under GEMM1)
    k_init<<<(NN + 255) / 256, 256, 0, s3>>>(ei);
    k_count<<<(E + 255) / 256, 256, 0, s3>>>(ei, E);
    k_part_sum<<<NB_SCAN, 256, 0, s3>>>();
    k_row_write<<<NB_SCAN, 256, 0, s3>>>(E);
    k_fill<<<(E + 255) / 256, 256, 0, s3>>>(ei, E);
    cudaEventRecord(eCSR, s3);

    int aggBlocks = (NN * 32 + 255) / 256;

    // main: GEMM1 x@[W1l|W1r] -> tb256/t256 (needs only conversions)
    cudaStreamWaitEvent(0, eCvtX, 0);
    cudaStreamWaitEvent(0, eCvtW, 0);
    {
        dim3 grid((NN + 127) / 128, 512 / 128);
        k_gemm_bf16<<<grid, 256, GEMM_SMEM>>>(0, 4, nullptr, /*outb=*/-1, NN, 512, 128, 0);
    }
    // combine1 (needs CSR): relu -> h1b
    cudaStreamWaitEvent(0, eCSR, 0);
    k_agg_combine<256, 0><<<aggBlocks, 256>>>(b1, nullptr, 2);
    // Layer 2
    {
        dim3 grid((NN + 127) / 128, 256 / 128);
        k_gemm_bf16<<<grid, 256, GEMM_SMEM>>>(2, 5, nullptr, /*outb=*/-1, NN, 256, 256, 0);
    }
    k_agg_combine<128, 0><<<aggBlocks, 256>>>(b2, nullptr, 3);
    // Layer 3
    {
        dim3 grid((NN + 127) / 128, 128 / 128);
        k_gemm_bf16<<<grid, 256, GEMM_SMEM>>>(3, 6, nullptr, /*outb=*/-1, NN, 128, 128, 0);
    }
    k_agg_combine<64, 1><<<aggBlocks, 256>>>(b3, out, -1);
}

// round 16
// speedup vs baseline: 1.1121x; 1.1121x over previous
#include <cuda_runtime.h>
#include <cuda_bf16.h>
#include <math.h>

#define NN 100000
#define EE 600000
#define NB_SCAN ((NN + 255) / 256)   // 391

// ---------------- static scratch (no allocations allowed) ----------------
__device__ int   g_is64;
__device__ int   g_deg[NN];
__device__ int   g_cur[NN];
__device__ int   g_rowstart[NN + 1];
__device__ int   g_col[EE];
__device__ int   g_part[512];

__device__ __nv_bfloat16 g_xb[(size_t)NN * 128];
__device__ __nv_bfloat16 g_meanb[(size_t)NN * 128];
__device__ __nv_bfloat16 g_h1b[(size_t)NN * 256];
__device__ __nv_bfloat16 g_h2b[(size_t)NN * 128];
__device__ __nv_bfloat16 g_tb[(size_t)NN * 128];   // bf16 mean-term (Wl half)
__device__ float         g_t[(size_t)NN * 128];    // fp32 self-term (Wr half)
__device__ __nv_bfloat16 g_wt1[256 * 256];
__device__ __nv_bfloat16 g_wt2[256 * 256];
__device__ __nv_bfloat16 g_wt3[128 * 128];

__device__ __forceinline__ __nv_bfloat16* bbuf(int id) {
    switch (id) {
        case 0: return g_xb;
        case 1: return g_meanb;
        case 2: return g_h1b;
        case 3: return g_h2b;
        case 4: return g_wt1;
        case 5: return g_wt2;
        default: return g_wt3;
    }
}

// ---------------- init: zero counts + dtype probe (fused) ----------------
__global__ void k_init(const int* __restrict__ w) {
    int i = blockIdx.x * blockDim.x + threadIdx.x;
    if (i < NN) { g_deg[i] = 0; g_cur[i] = 0; }
    if (i == 0) {
        int is64 = 1;
        for (int j = 0; j < 64; j++) {
            if (w[2 * j + 1] != 0) { is64 = 0; break; }
        }
        g_is64 = is64;
    }
}
__device__ __forceinline__ int edge_src(const int* w, int E, int e) {
    return g_is64 ? w[2 * e] : w[e];
}
__device__ __forceinline__ int edge_dst(const int* w, int E, int e) {
    return g_is64 ? w[2 * (E + e)] : w[E + e];
}

// ---------------- CSR build ----------------
__global__ void k_count(const int* __restrict__ w, int E) {
    int e = blockIdx.x * blockDim.x + threadIdx.x;
    if (e < E) atomicAdd(&g_deg[edge_dst(w, E, e)], 1);
}
__global__ void k_part_sum() {
    __shared__ int sm[8];
    int i = blockIdx.x * 256 + threadIdx.x;
    int v = (i < NN) ? g_deg[i] : 0;
#pragma unroll
    for (int off = 16; off; off >>= 1) v += __shfl_xor_sync(0xffffffffu, v, off);
    if ((threadIdx.x & 31) == 0) sm[threadIdx.x >> 5] = v;
    __syncthreads();
    if (threadIdx.x == 0) {
        int s = 0;
#pragma unroll
        for (int k = 0; k < 8; k++) s += sm[k];
        g_part[blockIdx.x] = s;
    }
}
__global__ void k_row_write(int E) {
    __shared__ int red[8];
    __shared__ int buf[256];
    __shared__ int base_sh;
    int t = threadIdx.x;
    int b = blockIdx.x;

    int acc = 0;
    for (int j = t; j < b; j += 256) acc += g_part[j];
#pragma unroll
    for (int off = 16; off; off >>= 1) acc += __shfl_xor_sync(0xffffffffu, acc, off);
    if ((t & 31) == 0) red[t >> 5] = acc;
    __syncthreads();
    if (t == 0) {
        int s = 0;
#pragma unroll
        for (int k = 0; k < 8; k++) s += red[k];
        base_sh = s;
    }

    int i = b * 256 + t;
    int d = (i < NN) ? g_deg[i] : 0;
    buf[t] = d;
    __syncthreads();
    for (int off = 1; off < 256; off <<= 1) {
        int v = (t >= off) ? buf[t - off] : 0;
        __syncthreads();
        buf[t] += v;
        __syncthreads();
    }
    if (i < NN) {
        g_rowstart[i] = base_sh + buf[t] - d;
        if (i == NN - 1) g_rowstart[NN] = E;
    }
}
__global__ void k_fill(const int* __restrict__ w, int E) {
    int e = blockIdx.x * blockDim.x + threadIdx.x;
    if (e < E) {
        int src = edge_src(w, E, e);
        int dst = edge_dst(w, E, e);
        int pos = g_rowstart[dst] + atomicAdd(&g_cur[dst], 1);
        g_col[pos] = src;
    }
}

// ---------------- conversions ----------------
__global__ void k_cvt_x(const float* __restrict__ x) {
    size_t i = (size_t)blockIdx.x * blockDim.x + threadIdx.x;
    if (i < (size_t)NN * 32) {
        float4 v = *(const float4*)(x + i * 4);
        __nv_bfloat162 o0, o1;
        o0.x = __float2bfloat16(v.x); o0.y = __float2bfloat16(v.y);
        o1.x = __float2bfloat16(v.z); o1.y = __float2bfloat16(v.w);
        uint2 ov;
        ov.x = *reinterpret_cast<unsigned*>(&o0);
        ov.y = *reinterpret_cast<unsigned*>(&o1);
        *(uint2*)(g_xb + i * 4) = ov;
    }
}
// Build transposed bf16 weight: dst[n*K2 + k].
// stackK=1: k<K2/2 -> Wl[k*N+n], else Wr[(k-K2/2)*N+n]
// stackK=0: n<N/2 -> Wl[k*(N/2)+n], else Wr[k*(N/2)+(n-N/2)]
__global__ void k_cvtw(const float* __restrict__ Wl, const float* __restrict__ Wr,
                       int dst_id, int K2, int N, int stackK) {
    int idx = blockIdx.x * blockDim.x + threadIdx.x;
    if (idx >= N * K2) return;
    int n = idx / K2, k = idx % K2;
    float v;
    if (stackK) {
        int half = K2 / 2;
        v = (k < half) ? Wl[(size_t)k * N + n] : Wr[(size_t)(k - half) * N + n];
    } else {
        int half = N / 2;
        v = (n < half) ? Wl[(size_t)k * half + n] : Wr[(size_t)k * half + (n - half)];
    }
    bbuf(dst_id)[(size_t)n * K2 + k] = __float2bfloat16(v);
}

// ---------------- L1 pre-aggregation (ILP-2) ----------------
__global__ void k_agg_pre() {
    int gw   = (blockIdx.x * blockDim.x + threadIdx.x) >> 5;
    int lane = threadIdx.x & 31;
    if (gw >= NN) return;
    int s = g_rowstart[gw], e = g_rowstart[gw + 1];
    float4 acc = make_float4(0.f, 0.f, 0.f, 0.f);
    int i = s;
    for (; i + 1 < e; i += 2) {
        int nb0 = g_col[i], nb1 = g_col[i + 1];
        uint2 va = *(const uint2*)(g_xb + (size_t)nb0 * 128 + lane * 4);
        uint2 vb = *(const uint2*)(g_xb + (size_t)nb1 * 128 + lane * 4);
        __nv_bfloat162 a0 = *reinterpret_cast<__nv_bfloat162*>(&va.x);
        __nv_bfloat162 a1 = *reinterpret_cast<__nv_bfloat162*>(&va.y);
        __nv_bfloat162 b0 = *reinterpret_cast<__nv_bfloat162*>(&vb.x);
        __nv_bfloat162 b1 = *reinterpret_cast<__nv_bfloat162*>(&vb.y);
        float2 fa0 = __bfloat1622float2(a0), fa1 = __bfloat1622float2(a1);
        float2 fb0 = __bfloat1622float2(b0), fb1 = __bfloat1622float2(b1);
        acc.x += fa0.x + fb0.x; acc.y += fa0.y + fb0.y;
        acc.z += fa1.x + fb1.x; acc.w += fa1.y + fb1.y;
    }
    if (i < e) {
        int nb = g_col[i];
        uint2 v = *(const uint2*)(g_xb + (size_t)nb * 128 + lane * 4);
        __nv_bfloat162 p0 = *reinterpret_cast<__nv_bfloat162*>(&v.x);
        __nv_bfloat162 p1 = *reinterpret_cast<__nv_bfloat162*>(&v.y);
        float2 f0 = __bfloat1622float2(p0);
        float2 f1 = __bfloat1622float2(p1);
        acc.x += f0.x; acc.y += f0.y; acc.z += f1.x; acc.w += f1.y;
    }
    float inv = 1.0f / (float)max(e - s, 1);
    __nv_bfloat162 o0, o1;
    o0.x = __float2bfloat16(acc.x * inv); o0.y = __float2bfloat16(acc.y * inv);
    o1.x = __float2bfloat16(acc.z * inv); o1.y = __float2bfloat16(acc.w * inv);
    uint2 ov;
    ov.x = *reinterpret_cast<unsigned*>(&o0);
    ov.y = *reinterpret_cast<unsigned*>(&o1);
    *(uint2*)(g_meanb + (size_t)gw * 128 + lane * 4) = ov;
}

// ---------------- bf16 GEMM: 3-stage cp.async + ldmatrix ----------------
// out[M,N] = [A0 | A1] @ Bt^T (+bias)(+relu), A k-split at Ka.
#define SA 40   // smem row stride in halves (80B): 16B-aligned, conflict-free
#define GEMM_SMEM (3 * 256 * SA * 2)   // 61440 bytes

__device__ __forceinline__ void cpa16(__nv_bfloat16* s, const void* g, int valid) {
    unsigned sa = (unsigned)__cvta_generic_to_shared(s);
    asm volatile("cp.async.cg.shared.global [%0], [%1], 16, %2;\n"
                 :: "r"(sa), "l"(g), "r"(valid ? 16 : 0));
}

__global__ void __launch_bounds__(256, 2)
k_gemm_bf16(int a0_id, int a1_id, int Ka, int b_id,
            const float* __restrict__ bias,
            int outb_id,          // >=0: bf16 out buffer id; <0: split bf16/fp32 out
            int M, int N, int K2, int do_relu) {
    const __nv_bfloat16* A0 = bbuf(a0_id);
    const __nv_bfloat16* A1 = bbuf(a1_id);
    const __nv_bfloat16* Bt = bbuf(b_id);
    const int sA0 = Ka, sA1 = K2 - Ka;

    constexpr int BM = 128, BN = 128, BK = 32;
    extern __shared__ __nv_bfloat16 dsm[];
    __nv_bfloat16* AsB = dsm;
    __nv_bfloat16* BsB = dsm + 3 * BM * SA;

    const int tid  = threadIdx.x;
    const int lane = tid & 31;
    const int warp = tid >> 5;
    const int wm   = warp & 3;
    const int wn   = warp >> 2;
    const int gid  = lane >> 2;
    const int tig  = lane & 3;

    const int blockRow = blockIdx.x * BM;
    const int blockCol = blockIdx.y * BN;

    float c[2][8][4];
#pragma unroll
    for (int mt = 0; mt < 2; mt++)
#pragma unroll
        for (int nt = 0; nt < 8; nt++)
#pragma unroll
            for (int r = 0; r < 4; r++) c[mt][nt][r] = 0.f;

    const int T = K2 / BK;

    auto load_tile = [&](int t, int stg) {
        __nv_bfloat16* As = AsB + stg * BM * SA;
        __nv_bfloat16* Bs = BsB + stg * BN * SA;
        const int kk = t * BK;
#pragma unroll
        for (int j = 0; j < 2; j++) {
            int f = tid + 256 * j;
            int r = f >> 2, c16 = f & 3;
            int gk = kk + c16 * 8;
            int grow = blockRow + r;
            int valid = grow < M;
            int rr = valid ? grow : 0;
            const __nv_bfloat16* p = (gk < Ka) ? (A0 + (size_t)rr * sA0 + gk)
                                               : (A1 + (size_t)rr * sA1 + (gk - Ka));
            cpa16(&As[r * SA + c16 * 8], p, valid);
        }
#pragma unroll
        for (int j = 0; j < 2; j++) {
            int f = tid + 256 * j;
            int r = f >> 2, c16 = f & 3;
            int gk = kk + c16 * 8;
            cpa16(&Bs[r * SA + c16 * 8], Bt + (size_t)(blockCol + r) * K2 + gk, 1);
        }
        asm volatile("cp.async.commit_group;\n");
    };

    load_tile(0, 0);
    if (T > 1) load_tile(1, 1);

    for (int t = 0; t < T; t++) {
        if (t + 1 < T) {
            asm volatile("cp.async.wait_group 1;\n");
        } else {
            asm volatile("cp.async.wait_group 0;\n");
        }
        __syncthreads();

        const int cur = t % 3;
        const __nv_bfloat16* as = AsB + cur * BM * SA;
        const __nv_bfloat16* bs = BsB + cur * BN * SA;

#pragma unroll
        for (int ks = 0; ks < BK; ks += 16) {
            unsigned af[2][4], bf[8][2];
#pragma unroll
            for (int mt = 0; mt < 2; mt++) {
                int row = wm * 32 + mt * 16 + (lane & 15);
                unsigned sa = (unsigned)__cvta_generic_to_shared(
                    as + row * SA + ks + (lane >> 4) * 8);
                asm volatile("ldmatrix.sync.aligned.m8n8.x4.shared.b16 {%0,%1,%2,%3}, [%4];"
                             : "=r"(af[mt][0]), "=r"(af[mt][1]),
                               "=r"(af[mt][2]), "=r"(af[mt][3])
                             : "r"(sa));
            }
#pragma unroll
            for (int np = 0; np < 4; np++) {
                int nrow = wn * 64 + np * 16 + (lane & 15);
                unsigned sb = (unsigned)__cvta_generic_to_shared(
                    bs + nrow * SA + ks + (lane >> 4) * 8);
                unsigned r0, r1, r2, r3;
                asm volatile("ldmatrix.sync.aligned.m8n8.x4.shared.b16 {%0,%1,%2,%3}, [%4];"
                             : "=r"(r0), "=r"(r1), "=r"(r2), "=r"(r3)
                             : "r"(sb));
                bf[2 * np + 0][0] = r0; bf[2 * np + 0][1] = r2;
                bf[2 * np + 1][0] = r1; bf[2 * np + 1][1] = r3;
            }
#pragma unroll
            for (int mt = 0; mt < 2; mt++)
#pragma unroll
                for (int nt = 0; nt < 8; nt++) {
                    asm volatile(
                        "mma.sync.aligned.m16n8k16.row.col.f32.bf16.bf16.f32 "
                        "{%0,%1,%2,%3}, {%4,%5,%6,%7}, {%8,%9}, {%0,%1,%2,%3};\n"
                        : "+f"(c[mt][nt][0]), "+f"(c[mt][nt][1]),
                          "+f"(c[mt][nt][2]), "+f"(c[mt][nt][3])
                        : "r"(af[mt][0]), "r"(af[mt][1]), "r"(af[mt][2]), "r"(af[mt][3]),
                          "r"(bf[nt][0]), "r"(bf[nt][1]));
                }
        }

        if (t + 2 < T) load_tile(t + 2, (t + 2) % 3);
    }

    // epilogue
    __nv_bfloat16* outb = (outb_id >= 0) ? bbuf(outb_id) : nullptr;
    const int half = N >> 1;
#pragma unroll
    for (int nt = 0; nt < 8; nt++) {
        int col = blockCol + wn * 64 + nt * 8 + 2 * tig;
        float bv0 = bias ? bias[col] : 0.f;
        float bv1 = bias ? bias[col + 1] : 0.f;
#pragma unroll
        for (int mt = 0; mt < 2; mt++) {
#pragma unroll
            for (int h = 0; h < 2; h++) {
                int r = blockRow + wm * 32 + mt * 16 + gid + h * 8;
                if (r < M) {
                    float v0 = c[mt][nt][2 * h + 0] + bv0;
                    float v1 = c[mt][nt][2 * h + 1] + bv1;
                    if (do_relu) { v0 = fmaxf(v0, 0.f); v1 = fmaxf(v1, 0.f); }
                    if (outb) {
                        __nv_bfloat162 o;
                        o.x = __float2bfloat16(v0);
                        o.y = __float2bfloat16(v1);
                        *(unsigned*)(outb + (size_t)r * N + col) =
                            *reinterpret_cast<unsigned*>(&o);
                    } else if (col < half) {
                        __nv_bfloat162 o;
                        o.x = __float2bfloat16(v0);
                        o.y = __float2bfloat16(v1);
                        *(unsigned*)(g_tb + (size_t)r * half + col) =
                            *reinterpret_cast<unsigned*>(&o);
                    } else {
                        float2 o = make_float2(v0, v1);
                        *(float2*)(g_t + (size_t)r * half + (col - half)) = o;
                    }
                }
            }
        }
    }
}

// ---------------- agg-combine: h = act(mean_nb(tb) + t_self + bias), ILP-2 ----------------
// MODE 0: relu -> bf16 g_h2b (C=128)
// MODE 1: log_softmax -> fp32 out (C=64)
template <int C, int MODE>
__global__ void k_agg_combine(const float* __restrict__ bias, float* __restrict__ out) {
    int gw   = (blockIdx.x * blockDim.x + threadIdx.x) >> 5;
    int lane = threadIdx.x & 31;
    if (gw >= NN) return;
    int s = g_rowstart[gw], e = g_rowstart[gw + 1];

    if constexpr (MODE == 0) {
        float4 acc = make_float4(0.f, 0.f, 0.f, 0.f);
        int i = s;
        for (; i + 1 < e; i += 2) {
            int nb0 = g_col[i], nb1 = g_col[i + 1];
            uint2 va = *(const uint2*)(g_tb + (size_t)nb0 * C + lane * 4);
            uint2 vb = *(const uint2*)(g_tb + (size_t)nb1 * C + lane * 4);
            __nv_bfloat162 a0 = *reinterpret_cast<__nv_bfloat162*>(&va.x);
            __nv_bfloat162 a1 = *reinterpret_cast<__nv_bfloat162*>(&va.y);
            __nv_bfloat162 b0 = *reinterpret_cast<__nv_bfloat162*>(&vb.x);
            __nv_bfloat162 b1 = *reinterpret_cast<__nv_bfloat162*>(&vb.y);
            float2 fa0 = __bfloat1622float2(a0), fa1 = __bfloat1622float2(a1);
            float2 fb0 = __bfloat1622float2(b0), fb1 = __bfloat1622float2(b1);
            acc.x += fa0.x + fb0.x; acc.y += fa0.y + fb0.y;
            acc.z += fa1.x + fb1.x; acc.w += fa1.y + fb1.y;
        }
        if (i < e) {
            int nb = g_col[i];
            uint2 va = *(const uint2*)(g_tb + (size_t)nb * C + lane * 4);
            __nv_bfloat162 a0 = *reinterpret_cast<__nv_bfloat162*>(&va.x);
            __nv_bfloat162 a1 = *reinterpret_cast<__nv_bfloat162*>(&va.y);
            float2 f0 = __bfloat1622float2(a0), f1 = __bfloat1622float2(a1);
            acc.x += f0.x; acc.y += f0.y; acc.z += f1.x; acc.w += f1.y;
        }
        float inv = 1.0f / (float)max(e - s, 1);
        float4 sv = *(const float4*)(g_t + (size_t)gw * C + lane * 4);
        float4 bv = *(const float4*)(bias + lane * 4);
        float v0 = fmaxf(acc.x * inv + sv.x + bv.x, 0.f);
        float v1 = fmaxf(acc.y * inv + sv.y + bv.y, 0.f);
        float v2 = fmaxf(acc.z * inv + sv.z + bv.z, 0.f);
        float v3 = fmaxf(acc.w * inv + sv.w + bv.w, 0.f);
        __nv_bfloat162 o0, o1;
        o0.x = __float2bfloat16(v0); o0.y = __float2bfloat16(v1);
        o1.x = __float2bfloat16(v2); o1.y = __float2bfloat16(v3);
        uint2 ov;
        ov.x = *reinterpret_cast<unsigned*>(&o0);
        ov.y = *reinterpret_cast<unsigned*>(&o1);
        *(uint2*)(g_h2b + (size_t)gw * C + lane * 4) = ov;
    } else {
        float2 acc = make_float2(0.f, 0.f);
        int i = s;
        for (; i + 1 < e; i += 2) {
            int nb0 = g_col[i], nb1 = g_col[i + 1];
            unsigned va = *(const unsigned*)(g_tb + (size_t)nb0 * C + lane * 2);
            unsigned vb = *(const unsigned*)(g_tb + (size_t)nb1 * C + lane * 2);
            __nv_bfloat162 pa = *reinterpret_cast<__nv_bfloat162*>(&va);
            __nv_bfloat162 pb = *reinterpret_cast<__nv_bfloat162*>(&vb);
            float2 fa = __bfloat1622float2(pa), fb = __bfloat1622float2(pb);
            acc.x += fa.x + fb.x; acc.y += fa.y + fb.y;
        }
        if (i < e) {
            int nb = g_col[i];
            unsigned v = *(const unsigned*)(g_tb + (size_t)nb * C + lane * 2);
            __nv_bfloat162 p = *reinterpret_cast<__nv_bfloat162*>(&v);
            float2 f = __bfloat1622float2(p);
            acc.x += f.x; acc.y += f.y;
        }
        float inv = 1.0f / (float)max(e - s, 1);
        float2 sv = *(const float2*)(g_t + (size_t)gw * C + lane * 2);
        float2 bv = *(const float2*)(bias + lane * 2);
        float v0 = acc.x * inv + sv.x + bv.x;
        float v1 = acc.y * inv + sv.y + bv.y;
        float m = fmaxf(v0, v1);
#pragma unroll
        for (int off = 16; off; off >>= 1) m = fmaxf(m, __shfl_xor_sync(0xffffffffu, m, off));
        float sum = __expf(v0 - m) + __expf(v1 - m);
#pragma unroll
        for (int off = 16; off; off >>= 1) sum += __shfl_xor_sync(0xffffffffu, sum, off);
        float lse = m + __logf(sum);
        float2 o = make_float2(v0 - lse, v1 - lse);
        *(float2*)(out + (size_t)gw * C + lane * 2) = o;
    }
}

// ---------------- launch ----------------
extern "C" void kernel_launch(void* const* d_in, const int* in_sizes, int n_in,
                              void* d_out, int out_size) {
    const float* x   = (const float*)d_in[0];
    const int*   ei  = (const int*)d_in[1];
    const float* W1l = (const float*)d_in[2];
    const float* W1r = (const float*)d_in[3];
    const float* b1  = (const float*)d_in[4];
    const float* W2l = (const float*)d_in[5];
    const float* W2r = (const float*)d_in[6];
    const float* b2  = (const float*)d_in[7];
    const float* W3l = (const float*)d_in[8];
    const float* W3r = (const float*)d_in[9];
    const float* b3  = (const float*)d_in[10];
    float* out = (float*)d_out;

    int E = in_sizes[1] / 2;

    static cudaStream_t s1 = nullptr, s2 = nullptr;
    static cudaEvent_t eFork = nullptr, eCvtX = nullptr, eCvtW = nullptr;
    if (!s1) {
        cudaStreamCreateWithFlags(&s1, cudaStreamNonBlocking);
        cudaStreamCreateWithFlags(&s2, cudaStreamNonBlocking);
        cudaEventCreateWithFlags(&eFork, cudaEventDisableTiming);
        cudaEventCreateWithFlags(&eCvtX, cudaEventDisableTiming);
        cudaEventCreateWithFlags(&eCvtW, cudaEventDisableTiming);
        cudaFuncSetAttribute(k_gemm_bf16,
                             cudaFuncAttributeMaxDynamicSharedMemorySize, GEMM_SMEM);
    }

    // fork
    cudaEventRecord(eFork, 0);
    cudaStreamWaitEvent(s1, eFork, 0);
    cudaStreamWaitEvent(s2, eFork, 0);

    // s1: x -> bf16
    k_cvt_x<<<(NN * 32 + 255) / 256, 256, 0, s1>>>(x);
    cudaEventRecord(eCvtX, s1);

    // s2: weight transposes -> bf16
    k_cvtw<<<(256 * 256 + 255) / 256, 256, 0, s2>>>(W1l, W1r, 4, 256, 256, 1);
    k_cvtw<<<(256 * 256 + 255) / 256, 256, 0, s2>>>(W2l, W2r, 5, 256, 256, 0);
    k_cvtw<<<(128 * 128 + 255) / 256, 256, 0, s2>>>(W3l, W3r, 6, 128, 128, 0);
    cudaEventRecord(eCvtW, s2);

    // main stream: CSR build (overlaps conversions)
    k_init<<<(NN + 255) / 256, 256>>>(ei);
    k_count<<<(E + 255) / 256, 256>>>(ei, E);
    k_part_sum<<<NB_SCAN, 256>>>();
    k_row_write<<<NB_SCAN, 256>>>(E);
    k_fill<<<(E + 255) / 256, 256>>>(ei, E);

    cudaStreamWaitEvent(0, eCvtX, 0);

    int aggBlocks = (NN * 32 + 255) / 256;

    // Layer 1: pre-agg + dual-A GEMM -> h1b (relu)
    k_agg_pre<<<aggBlocks, 256>>>();
    cudaStreamWaitEvent(0, eCvtW, 0);
    {
        dim3 grid((NN + 127) / 128, 256 / 128);
        k_gemm_bf16<<<grid, 256, GEMM_SMEM>>>(1, 0, 128, 4, b1, /*outb=*/2, NN, 256, 256, 1);
    }
    // Layer 2: GEMM -> split tb/t, agg-combine(relu) -> h2b
    {
        dim3 grid((NN + 127) / 128, 256 / 128);
        k_gemm_bf16<<<grid, 256, GEMM_SMEM>>>(2, 2, 256, 5, nullptr, /*outb=*/-1, NN, 256, 256, 0);
    }
    k_agg_combine<128, 0><<<aggBlocks, 256>>>(b2, nullptr);
    // Layer 3: GEMM -> split tb/t, agg-combine + log_softmax -> out
    {
        dim3 grid((NN + 127) / 128, 128 / 128);
        k_gemm_bf16<<<grid, 256, GEMM_SMEM>>>(3, 3, 128, 6, nullptr, /*outb=*/-1, NN, 128, 128, 0);
    }
    k_agg_combine<64, 1><<<aggBlocks, 256>>>(b3, out);
}